// round 2
// baseline (speedup 1.0000x reference)
#include <cuda_runtime.h>
#include <cstdint>
#include <cstddef>

#define NCH 128
#define MAXN 50000

// ---------------- scratch (static device arrays; no allocation) ----------------
__device__ float g_h[(size_t)MAXN * NCH];
__device__ float g_agg[(size_t)MAXN * NCH];
__device__ float g_t[(size_t)MAXN * NCH];
__device__ int   g_is64;

// ---------------- helpers ----------------
__device__ __forceinline__ unsigned f2tf(float f) {
    unsigned u;
    asm("cvt.rna.tf32.f32 %0, %1;" : "=r"(u) : "f"(f));
    return u;
}

__device__ __forceinline__ void mma8(float c[4],
                                     unsigned a0, unsigned a1, unsigned a2, unsigned a3,
                                     unsigned b0, unsigned b1) {
    asm volatile(
        "mma.sync.aligned.m16n8k8.row.col.f32.tf32.tf32.f32 "
        "{%0,%1,%2,%3},{%4,%5,%6,%7},{%8,%9},{%0,%1,%2,%3};\n"
        : "+f"(c[0]), "+f"(c[1]), "+f"(c[2]), "+f"(c[3])
        : "r"(a0), "r"(a1), "r"(a2), "r"(a3), "r"(b0), "r"(b1));
}

__device__ __forceinline__ float gelu_exact(float x) {
    return 0.5f * x * (1.0f + erff(x * 0.70710678118654752f));
}

// sin/cos with explicit Cody-Waite reduction mod 2*pi (fast-math safe)
__device__ __forceinline__ float sin_acc(float x) {
    const float INV2PI = 0.15915494309189535f;
    const float A = 6.2831854820251465f;
    const float B = -1.7484555e-7f;
    float n = rintf(x * INV2PI);
    float r = fmaf(-n, A, x);
    r = fmaf(-n, B, r);
    return sinf(r);
}
__device__ __forceinline__ float cos_acc(float x) {
    const float INV2PI = 0.15915494309189535f;
    const float A = 6.2831854820251465f;
    const float B = -1.7484555e-7f;
    float n = rintf(x * INV2PI);
    float r = fmaf(-n, A, x);
    r = fmaf(-n, B, r);
    return cosf(r);
}

// ---------------- packed fragment stores ----------------
// A packed: per (k8-step s, m16-tile t): thread lane's frag (a0,a1,a2,a3) contiguous
//   a0=(r,c) a1=(r+8,c) a2=(r,c+4) a3=(r+8,c+4); lane=(r&7)*4 + c
__device__ __forceinline__ void pack_store_A(float* sA, int row, int kloc, float v) {
    int t = row >> 4, rg = (row >> 3) & 1, r8 = row & 7;
    int s = kloc >> 3, c = kloc & 3, h = (kloc >> 2) & 1;
    int idx = (((s * 8 + t) * 32) + r8 * 4 + c) * 4 + h * 2 + rg;
    ((unsigned*)sA)[idx] = f2tf(v);
}
// B packed: per (k8-step s, n8-tile u): thread lane's frag (b0,b1) contiguous
//   b0=(k,n) b1=(k+4,n); lane=(n&7)*4 + (k&3)
__device__ __forceinline__ void pack_store_B(float* sB, int k, int n, float v) {
    int s = k >> 3, u = n >> 3, e = (k >> 2) & 1;
    int idx = ((s * 16 + u) * 32 + (n & 7) * 4 + (k & 3)) * 2 + e;
    ((unsigned*)sB)[idx] = f2tf(v);
}

// consume one K=32 chunk: A packed (sbase = k8 offset within sAp), B packed chunk
__device__ __forceinline__ void mma_chunk(float acc[4][4][4], const float* sAp, int sbase,
                                          const float* sB, int wm, int wn, int lane) {
    const uint4* A4 = (const uint4*)sAp;
    const uint2* B2 = (const uint2*)sB;
#pragma unroll
    for (int kk = 0; kk < 4; kk++) {
        uint2 bf[4];
#pragma unroll
        for (int nt = 0; nt < 4; nt++)
            bf[nt] = B2[(kk * 16 + wn * 4 + nt) * 32 + lane];
#pragma unroll
        for (int mt = 0; mt < 4; mt++) {
            uint4 a = A4[((sbase + kk) * 8 + wm * 4 + mt) * 32 + lane];
#pragma unroll
            for (int nt = 0; nt < 4; nt++)
                mma8(acc[mt][nt], a.x, a.y, a.z, a.w, bf[nt].x, bf[nt].y);
        }
    }
}

__device__ __forceinline__ void init_acc(float acc[4][4][4], const float* sBias, int wn, int lane) {
#pragma unroll
    for (int nt = 0; nt < 4; nt++) {
        int c = wn * 32 + nt * 8 + (lane & 3) * 2;
        float x0 = sBias[c], x1 = sBias[c + 1];
#pragma unroll
        for (int mt = 0; mt < 4; mt++) {
            acc[mt][nt][0] = x0; acc[mt][nt][1] = x1;
            acc[mt][nt][2] = x0; acc[mt][nt][3] = x1;
        }
    }
}

// epilogue -> packed-A layout of sMp (for the next stage's A operand)
__device__ __forceinline__ void epi_packed(float acc[4][4][4], float* sMp,
                                           int wm, int wn, int lane) {
#pragma unroll
    for (int mt = 0; mt < 4; mt++) {
        int r0 = wm * 64 + mt * 16 + (lane >> 2);
#pragma unroll
        for (int nt = 0; nt < 4; nt++) {
            int c0 = wn * 32 + nt * 8 + (lane & 3) * 2;
            float v0 = gelu_exact(acc[mt][nt][0]);
            float v1 = gelu_exact(acc[mt][nt][1]);
            float v2 = gelu_exact(acc[mt][nt][2]);
            float v3 = gelu_exact(acc[mt][nt][3]);
            pack_store_A(sMp, r0, c0, v0);
            pack_store_A(sMp, r0, c0 + 1, v1);
            pack_store_A(sMp, r0 + 8, c0, v2);
            pack_store_A(sMp, r0 + 8, c0 + 1, v3);
        }
    }
}

// ---------------- misc kernels ----------------
__global__ void zero_kernel(float4* p, int n4) {
    int i = blockIdx.x * blockDim.x + threadIdx.x;
    if (i < n4) p[i] = make_float4(0.f, 0.f, 0.f, 0.f);
}

__global__ void detect_kernel(const void* ei) {
    const long long* p = (const long long*)ei;
    bool is64 = true;
    for (int i = 0; i < 8; i++) {
        long long v = p[i];
        if (v < 0 || v >= (1LL << 31)) is64 = false;
    }
    g_is64 = is64 ? 1 : 0;
}

// ---------------- tf32 node GEMM:  C = act(A (+A2) @ W + bias) ----------------
__global__ void __launch_bounds__(256)
node_gemm(const float* __restrict__ A, const float* __restrict__ A2,
          const float* __restrict__ W, const float* __restrict__ bias,
          float* __restrict__ C, int M, int act) {
    __shared__ float sA[4096];
    __shared__ float sB[4096];
    const int tid = threadIdx.x;
    const int lane = tid & 31;
    const int warp = tid >> 5;
    const int wm = warp >> 2, wn = warp & 3;
    const int m0 = blockIdx.x * 128;

    float acc[4][4][4];
#pragma unroll
    for (int nt = 0; nt < 4; nt++) {
        int c = wn * 32 + nt * 8 + (lane & 3) * 2;
        float x0 = __ldg(bias + c), x1 = __ldg(bias + c + 1);
#pragma unroll
        for (int mt = 0; mt < 4; mt++) {
            acc[mt][nt][0] = x0; acc[mt][nt][1] = x1;
            acc[mt][nt][2] = x0; acc[mt][nt][3] = x1;
        }
    }

#pragma unroll 1
    for (int kc = 0; kc < 4; kc++) {
#pragma unroll
        for (int i = 0; i < 4; i++) {
            int lin = tid + i * 256;
            int row = lin >> 3, c4 = lin & 7;
            float4 v = make_float4(0.f, 0.f, 0.f, 0.f);
            if (m0 + row < M) {
                v = *(const float4*)(A + (size_t)(m0 + row) * NCH + kc * 32 + c4 * 4);
                if (A2) {
                    float4 w = *(const float4*)(A2 + (size_t)(m0 + row) * NCH + kc * 32 + c4 * 4);
                    v.x += w.x; v.y += w.y; v.z += w.z; v.w += w.w;
                }
            }
            pack_store_A(sA, row, c4 * 4 + 0, v.x);
            pack_store_A(sA, row, c4 * 4 + 1, v.y);
            pack_store_A(sA, row, c4 * 4 + 2, v.z);
            pack_store_A(sA, row, c4 * 4 + 3, v.w);
        }
#pragma unroll
        for (int i = 0; i < 4; i++) {
            int lin = tid + i * 256;
            int kr = lin >> 5, n4 = lin & 31;
            float4 v = *(const float4*)(W + (size_t)(kc * 32 + kr) * NCH + n4 * 4);
            pack_store_B(sB, kr, n4 * 4 + 0, v.x);
            pack_store_B(sB, kr, n4 * 4 + 1, v.y);
            pack_store_B(sB, kr, n4 * 4 + 2, v.z);
            pack_store_B(sB, kr, n4 * 4 + 3, v.w);
        }
        __syncthreads();
        mma_chunk(acc, sA, 0, sB, wm, wn, lane);
        __syncthreads();
    }

#pragma unroll
    for (int mt = 0; mt < 4; mt++) {
        int r0 = m0 + wm * 64 + mt * 16 + (lane >> 2);
#pragma unroll
        for (int nt = 0; nt < 4; nt++) {
            int c0 = wn * 32 + nt * 8 + (lane & 3) * 2;
            float v0 = acc[mt][nt][0], v1 = acc[mt][nt][1];
            float v2 = acc[mt][nt][2], v3 = acc[mt][nt][3];
            if (act) {
                v0 = fmaxf(v0, 0.f); v1 = fmaxf(v1, 0.f);
                v2 = fmaxf(v2, 0.f); v3 = fmaxf(v3, 0.f);
            }
            if (r0 < M) *(float2*)(C + (size_t)r0 * NCH + c0) = make_float2(v0, v1);
            if (r0 + 8 < M) *(float2*)(C + (size_t)(r0 + 8) * NCH + c0) = make_float2(v2, v3);
        }
    }
}

// ---------------- fused edge kernel ----------------
// smem (floats): sMp 16896 | sA 4096 | sB 4096 | sR 128 | sBias 128 | sSrc 128 | sDst 128
#define SMEM_EDGE_BYTES ((16896 + 4096 + 4096 + 128 + 128 + 128 + 128) * 4)
#define SM_STRIDE 132   // row-major stride for final m buffer (re-uses sMp)

__global__ void __launch_bounds__(256)
edge_kernel(const void* __restrict__ ei_raw, const float* __restrict__ eattr,
            const float* __restrict__ xpos, const float* __restrict__ h,
            float* __restrict__ agg,
            const float* __restrict__ mw1, const float* __restrict__ mb1,
            const float* __restrict__ mw2, const float* __restrict__ mb2,
            const float* __restrict__ mw3, const float* __restrict__ mb3,
            int E) {
    extern __shared__ float smem[];
    float* sMp = smem;                 // 16896 (packed inter-stage A; later row-major m)
    float* sA = sMp + 16896;           // 4096 (stage-1 A chunk, packed)
    float* sB = sA + 4096;             // 4096 (weight chunk, packed)
    float* sR = sB + 4096;             // 128
    float* sBias = sR + 128;           // 128
    int* sSrc = (int*)(sBias + 128);
    int* sDst = sSrc + 128;

    const int tid = threadIdx.x;
    const int lane = tid & 31;
    const int warp = tid >> 5;
    const int wm = warp >> 2, wn = warp & 3;
    const int e0 = blockIdx.x * 128;
    const int is64 = g_is64;

    // prologue
    if (tid < 128) {
        int e = e0 + tid;
        int s = 0, d = -1;
        float r = 0.f;
        if (e < E) {
            if (is64) {
                const long long* p = (const long long*)ei_raw;
                s = (int)p[e];
                d = (int)p[(size_t)E + e];
            } else {
                const int* p = (const int*)ei_raw;
                s = p[e];
                d = p[(size_t)E + e];
            }
            float dx = xpos[3 * d + 0] - xpos[3 * s + 0];
            float dy = xpos[3 * d + 1] - xpos[3 * s + 1];
            float dz = xpos[3 * d + 2] - xpos[3 * s + 2];
            r = sqrtf(dx * dx + dy * dy + dz * dz);
        }
        sSrc[tid] = s;
        sDst[tid] = d;
        sR[tid] = r;
        sBias[tid] = mb1[tid];
    }
    __syncthreads();

    float acc[4][4][4];
    init_acc(acc, sBias, wn, lane);

    // ---------------- stage 1: [128 x 288] @ mw1 + mb1, gelu ----------------
#pragma unroll 1
    for (int kc = 0; kc < 9; kc++) {
        if (kc == 0) {
            // sin/cos features, written directly in packed order (STS128)
#pragma unroll
            for (int i = 0; i < 4; i++) {
                int q = tid + i * 256;
                int lq = q & 31, t = (q >> 5) & 7, s = q >> 8;
                int r0 = t * 16 + (lq >> 2);
                int k0 = s * 8 + (lq & 3);
                int k1 = k0 + 4;
                float rA = sR[r0], rB = sR[r0 + 8];
                float w0 = 10.f * exp2f(7.f - 0.875f * (float)(k0 & 15));
                float w1 = 10.f * exp2f(7.f - 0.875f * (float)(k1 & 15));
                float v0, v1, v2, v3;
                if (k0 < 16) { v0 = sin_acc(rA * w0); v1 = sin_acc(rB * w0); }
                else         { v0 = cos_acc(rA * w0); v1 = cos_acc(rB * w0); }
                if (k1 < 16) { v2 = sin_acc(rA * w1); v3 = sin_acc(rB * w1); }
                else         { v2 = cos_acc(rA * w1); v3 = cos_acc(rB * w1); }
                uint4 u;
                u.x = f2tf(v0); u.y = f2tf(v1); u.z = f2tf(v2); u.w = f2tf(v3);
                ((uint4*)sA)[(s * 8 + t) * 32 + lq] = u;
            }
        } else if (kc <= 4) {
            // edge_attr cols (32..159): coalesced LDG128, scatter to packed
#pragma unroll
            for (int i = 0; i < 4; i++) {
                int lin = tid + i * 256;
                int row = lin >> 3, c4 = lin & 7;
                float4 v = make_float4(0.f, 0.f, 0.f, 0.f);
                int e = e0 + row;
                if (e < E)
                    v = *(const float4*)(eattr + (size_t)e * NCH + (kc - 1) * 32 + c4 * 4);
                pack_store_A(sA, row, c4 * 4 + 0, v.x);
                pack_store_A(sA, row, c4 * 4 + 1, v.y);
                pack_store_A(sA, row, c4 * 4 + 2, v.z);
                pack_store_A(sA, row, c4 * 4 + 3, v.w);
            }
        } else {
            // h[src] gather (cols 160..287)
#pragma unroll
            for (int i = 0; i < 4; i++) {
                int lin = tid + i * 256;
                int row = lin >> 3, c4 = lin & 7;
                int s = sSrc[row];
                float4 v = *(const float4*)(h + (size_t)s * NCH + (kc - 5) * 32 + c4 * 4);
                pack_store_A(sA, row, c4 * 4 + 0, v.x);
                pack_store_A(sA, row, c4 * 4 + 1, v.y);
                pack_store_A(sA, row, c4 * 4 + 2, v.z);
                pack_store_A(sA, row, c4 * 4 + 3, v.w);
            }
        }
        // weight chunk
        const float* Wp = mw1 + (size_t)kc * 32 * NCH;
#pragma unroll
        for (int i = 0; i < 4; i++) {
            int lin = tid + i * 256;
            int kr = lin >> 5, n4 = lin & 31;
            float4 v = *(const float4*)(Wp + (size_t)kr * NCH + n4 * 4);
            pack_store_B(sB, kr, n4 * 4 + 0, v.x);
            pack_store_B(sB, kr, n4 * 4 + 1, v.y);
            pack_store_B(sB, kr, n4 * 4 + 2, v.z);
            pack_store_B(sB, kr, n4 * 4 + 3, v.w);
        }
        __syncthreads();
        mma_chunk(acc, sA, 0, sB, wm, wn, lane);
        __syncthreads();
    }
    epi_packed(acc, sMp, wm, wn, lane);
    if (tid < 128) sBias[tid] = mb2[tid];
    __syncthreads();

    // ---------------- stage 2: K=128, A resident packed in sMp ----------------
    init_acc(acc, sBias, wn, lane);
#pragma unroll 1
    for (int kc = 0; kc < 4; kc++) {
        const float* Wp = mw2 + (size_t)kc * 32 * NCH;
#pragma unroll
        for (int i = 0; i < 4; i++) {
            int lin = tid + i * 256;
            int kr = lin >> 5, n4 = lin & 31;
            float4 v = *(const float4*)(Wp + (size_t)kr * NCH + n4 * 4);
            pack_store_B(sB, kr, n4 * 4 + 0, v.x);
            pack_store_B(sB, kr, n4 * 4 + 1, v.y);
            pack_store_B(sB, kr, n4 * 4 + 2, v.z);
            pack_store_B(sB, kr, n4 * 4 + 3, v.w);
        }
        __syncthreads();
        mma_chunk(acc, sMp, kc * 4, sB, wm, wn, lane);
        __syncthreads();
    }
    epi_packed(acc, sMp, wm, wn, lane);
    if (tid < 128) sBias[tid] = mb3[tid];
    __syncthreads();

    // ---------------- stage 3: K=128, no gelu ----------------
    init_acc(acc, sBias, wn, lane);
#pragma unroll 1
    for (int kc = 0; kc < 4; kc++) {
        const float* Wp = mw3 + (size_t)kc * 32 * NCH;
#pragma unroll
        for (int i = 0; i < 4; i++) {
            int lin = tid + i * 256;
            int kr = lin >> 5, n4 = lin & 31;
            float4 v = *(const float4*)(Wp + (size_t)kr * NCH + n4 * 4);
            pack_store_B(sB, kr, n4 * 4 + 0, v.x);
            pack_store_B(sB, kr, n4 * 4 + 1, v.y);
            pack_store_B(sB, kr, n4 * 4 + 2, v.z);
            pack_store_B(sB, kr, n4 * 4 + 3, v.w);
        }
        __syncthreads();
        mma_chunk(acc, sMp, kc * 4, sB, wm, wn, lane);
        __syncthreads();
    }
    // stage-3 epilogue: row-major into sMp (stride 132), fp32, no gelu
#pragma unroll
    for (int mt = 0; mt < 4; mt++) {
        int r0 = wm * 64 + mt * 16 + (lane >> 2);
#pragma unroll
        for (int nt = 0; nt < 4; nt++) {
            int c0 = wn * 32 + nt * 8 + (lane & 3) * 2;
            *(float2*)&sMp[r0 * SM_STRIDE + c0] = make_float2(acc[mt][nt][0], acc[mt][nt][1]);
            *(float2*)&sMp[(r0 + 8) * SM_STRIDE + c0] = make_float2(acc[mt][nt][2], acc[mt][nt][3]);
        }
    }
    __syncthreads();

    // ---------------- scatter: agg[dst] += m ----------------
#pragma unroll
    for (int i = 0; i < 16; i++) {
        int lin = tid + i * 256;
        int row = lin >> 5, c4 = lin & 31;
        int d = sDst[row];
        if (d >= 0) {
            float4 v = *(float4*)&sMp[row * SM_STRIDE + c4 * 4];
            float* p = agg + (size_t)d * NCH + c4 * 4;
            asm volatile("red.global.add.v4.f32 [%0], {%1,%2,%3,%4};" ::
                             "l"(p), "f"(v.x), "f"(v.y), "f"(v.z), "f"(v.w)
                         : "memory");
        }
    }
}

// ---------------- launch ----------------
extern "C" void kernel_launch(void* const* d_in, const int* in_sizes, int n_in,
                              void* d_out, int out_size) {
    const float* x     = (const float*)d_in[0];
    const void*  ei    = d_in[1];
    const float* eattr = (const float*)d_in[2];
    const float* xpos  = (const float*)d_in[3];
    const float* w1  = (const float*)d_in[4];
    const float* b1  = (const float*)d_in[5];
    const float* mw1 = (const float*)d_in[6];
    const float* mb1 = (const float*)d_in[7];
    const float* mw2 = (const float*)d_in[8];
    const float* mb2 = (const float*)d_in[9];
    const float* mw3 = (const float*)d_in[10];
    const float* mb3 = (const float*)d_in[11];
    const float* w2  = (const float*)d_in[12];
    const float* b2  = (const float*)d_in[13];
    const float* w3  = (const float*)d_in[14];
    const float* b3  = (const float*)d_in[15];

    int N = in_sizes[0] / NCH;
    int E = in_sizes[1] / 2;
    float* out = (float*)d_out;

    float *hptr, *aptr, *tptr;
    cudaGetSymbolAddress((void**)&hptr, g_h);
    cudaGetSymbolAddress((void**)&aptr, g_agg);
    cudaGetSymbolAddress((void**)&tptr, g_t);

    cudaFuncSetAttribute(edge_kernel, cudaFuncAttributeMaxDynamicSharedMemorySize,
                         SMEM_EDGE_BYTES);

    detect_kernel<<<1, 1>>>(ei);

    int n4 = N * NCH / 4;
    zero_kernel<<<(n4 + 255) / 256, 256>>>((float4*)aptr, n4);

    node_gemm<<<(N + 127) / 128, 256>>>(x, nullptr, w1, b1, hptr, N, 0);

    edge_kernel<<<(E + 127) / 128, 256, SMEM_EDGE_BYTES>>>(
        ei, eattr, xpos, hptr, aptr, mw1, mb1, mw2, mb2, mw3, mb3, E);

    node_gemm<<<(N + 127) / 128, 256>>>(hptr, aptr, w2, b2, tptr, N, 1);
    node_gemm<<<(N + 127) / 128, 256>>>(tptr, nullptr, w3, b3, out, N, 0);
}

// round 3
// speedup vs baseline: 2.9406x; 2.9406x over previous
#include <cuda_runtime.h>
#include <cstdint>
#include <cstddef>

#define NCH 128
#define MAXN 50000

// ---------------- scratch (static device arrays; no allocation) ----------------
__device__ float g_h[(size_t)MAXN * NCH];
__device__ float g_agg[(size_t)MAXN * NCH];
__device__ float g_t[(size_t)MAXN * NCH];
__device__ unsigned g_wpack[118784];   // tf32 fragment-packed weights
__device__ int   g_is64;

// packed-weight offsets (in words)
#define OFF_MW1 0        // 9 chunks * 4096
#define OFF_MW2 36864    // 4 chunks
#define OFF_MW3 53248
#define OFF_W1  69632
#define OFF_W2  86016
#define OFF_W3  102400

// ---------------- helpers ----------------
__device__ __forceinline__ unsigned f2tf(float f) {
    unsigned u;
    asm("cvt.rna.tf32.f32 %0, %1;" : "=r"(u) : "f"(f));
    return u;
}

__device__ __forceinline__ void mma8(float c[4],
                                     unsigned a0, unsigned a1, unsigned a2, unsigned a3,
                                     unsigned b0, unsigned b1) {
    asm volatile(
        "mma.sync.aligned.m16n8k8.row.col.f32.tf32.tf32.f32 "
        "{%0,%1,%2,%3},{%4,%5,%6,%7},{%8,%9},{%0,%1,%2,%3};\n"
        : "+f"(c[0]), "+f"(c[1]), "+f"(c[2]), "+f"(c[3])
        : "r"(a0), "r"(a1), "r"(a2), "r"(a3), "r"(b0), "r"(b1));
}

__device__ __forceinline__ float gelu_exact(float x) {
    return 0.5f * x * (1.0f + erff(x * 0.70710678118654752f));
}

// ---------------- mainloop: one K=32 chunk, A row-major tf32 in smem, B packed ----
// A: row-major, 'stride' words per row, values already tf32 bits.
// B: packed chunk: uint2 per (kk, n8-tile u, lane): word ((kk*16+u)*32+lane)*2+e
__device__ __forceinline__ void mma_chunk_rm(float acc[4][4][4],
                                             const unsigned* __restrict__ sA, int stride, int kbase,
                                             const unsigned* __restrict__ sB,
                                             int wm, int wn, int lane) {
    const uint2* B2 = (const uint2*)sB;
#pragma unroll
    for (int kk = 0; kk < 4; kk++) {
        uint2 bf[4];
#pragma unroll
        for (int nt = 0; nt < 4; nt++)
            bf[nt] = B2[(kk * 16 + wn * 4 + nt) * 32 + lane];
#pragma unroll
        for (int mt = 0; mt < 4; mt++) {
            const unsigned* ap = sA + (wm * 64 + mt * 16 + (lane >> 2)) * stride
                                 + kbase + kk * 8 + (lane & 3);
            unsigned a0 = ap[0];
            unsigned a1 = ap[8 * stride];
            unsigned a2 = ap[4];
            unsigned a3 = ap[8 * stride + 4];
#pragma unroll
            for (int nt = 0; nt < 4; nt++)
                mma8(acc[mt][nt], a0, a1, a2, a3, bf[nt].x, bf[nt].y);
        }
    }
}

__device__ __forceinline__ void init_acc(float acc[4][4][4], const float* sBias, int wn, int lane) {
#pragma unroll
    for (int nt = 0; nt < 4; nt++) {
        int c = wn * 32 + nt * 8 + (lane & 3) * 2;
        float x0 = sBias[c], x1 = sBias[c + 1];
#pragma unroll
        for (int mt = 0; mt < 4; mt++) {
            acc[mt][nt][0] = x0; acc[mt][nt][1] = x1;
            acc[mt][nt][2] = x0; acc[mt][nt][3] = x1;
        }
    }
}

// epilogue -> row-major tf32 (gelu applied), for next stage's A
__device__ __forceinline__ void epi_tf32_gelu(float acc[4][4][4], unsigned* sM, int stride,
                                              int wm, int wn, int lane) {
#pragma unroll
    for (int mt = 0; mt < 4; mt++) {
        int r0 = wm * 64 + mt * 16 + (lane >> 2);
#pragma unroll
        for (int nt = 0; nt < 4; nt++) {
            int c0 = wn * 32 + nt * 8 + (lane & 3) * 2;
            uint2 u0, u1;
            u0.x = f2tf(gelu_exact(acc[mt][nt][0]));
            u0.y = f2tf(gelu_exact(acc[mt][nt][1]));
            u1.x = f2tf(gelu_exact(acc[mt][nt][2]));
            u1.y = f2tf(gelu_exact(acc[mt][nt][3]));
            *(uint2*)&sM[r0 * stride + c0] = u0;
            *(uint2*)&sM[(r0 + 8) * stride + c0] = u1;
        }
    }
}

// ---------------- misc kernels ----------------
__global__ void zero_kernel(float4* p, int n4) {
    int i = blockIdx.x * blockDim.x + threadIdx.x;
    if (i < n4) p[i] = make_float4(0.f, 0.f, 0.f, 0.f);
}

__global__ void detect_kernel(const void* ei) {
    const long long* p = (const long long*)ei;
    bool is64 = true;
    for (int i = 0; i < 8; i++) {
        long long v = p[i];
        if (v < 0 || v >= (1LL << 31)) is64 = false;
    }
    g_is64 = is64 ? 1 : 0;
}

// pre-pack a [K x 128] weight into tf32 fragment order
__global__ void pack_w(const float* __restrict__ src, unsigned* __restrict__ dst, int nwords) {
    int idx = blockIdx.x * blockDim.x + threadIdx.x;
    if (idx >= nwords) return;
    int e = idx & 1;
    int lane = (idx >> 1) & 31;
    int u = (idx >> 6) & 15;
    int kk = (idx >> 10) & 3;
    int kc = idx >> 12;
    int k = kc * 32 + kk * 8 + e * 4 + (lane & 3);
    int n = u * 8 + (lane >> 2);
    dst[idx] = f2tf(src[(size_t)k * NCH + n]);
}

// ---------------- tf32 node GEMM:  C = act(A (+A2) @ W + bias) ----------------
__global__ void __launch_bounds__(256, 2)
node_gemm(const float* __restrict__ A, const float* __restrict__ A2,
          const unsigned* __restrict__ Wp, const float* __restrict__ bias,
          float* __restrict__ C, int M, int act) {
    __shared__ __align__(16) unsigned sA[128 * 36];
    __shared__ __align__(16) unsigned sB[4096];
    __shared__ float sBias[128];
    const int tid = threadIdx.x;
    const int lane = tid & 31;
    const int warp = tid >> 5;
    const int wm = warp >> 2, wn = warp & 3;
    const int m0 = blockIdx.x * 128;

    if (tid < 128) sBias[tid] = bias[tid];
    __syncthreads();

    float acc[4][4][4];
    init_acc(acc, sBias, wn, lane);

#pragma unroll 1
    for (int kc = 0; kc < 4; kc++) {
#pragma unroll
        for (int i = 0; i < 4; i++) {
            int lin = tid + i * 256;
            int row = lin >> 3, c4 = lin & 7;
            float4 v = make_float4(0.f, 0.f, 0.f, 0.f);
            if (m0 + row < M) {
                v = *(const float4*)(A + (size_t)(m0 + row) * NCH + kc * 32 + c4 * 4);
                if (A2) {
                    float4 w = *(const float4*)(A2 + (size_t)(m0 + row) * NCH + kc * 32 + c4 * 4);
                    v.x += w.x; v.y += w.y; v.z += w.z; v.w += w.w;
                }
            }
            uint4 u;
            u.x = f2tf(v.x); u.y = f2tf(v.y); u.z = f2tf(v.z); u.w = f2tf(v.w);
            *(uint4*)&sA[row * 36 + c4 * 4] = u;
        }
        const uint4* bs = (const uint4*)(Wp + (size_t)kc * 4096);
#pragma unroll
        for (int i = 0; i < 4; i++)
            ((uint4*)sB)[tid + i * 256] = bs[tid + i * 256];
        __syncthreads();
        mma_chunk_rm(acc, sA, 36, 0, sB, wm, wn, lane);
        __syncthreads();
    }

#pragma unroll
    for (int mt = 0; mt < 4; mt++) {
        int r0 = m0 + wm * 64 + mt * 16 + (lane >> 2);
#pragma unroll
        for (int nt = 0; nt < 4; nt++) {
            int c0 = wn * 32 + nt * 8 + (lane & 3) * 2;
            float v0 = acc[mt][nt][0], v1 = acc[mt][nt][1];
            float v2 = acc[mt][nt][2], v3 = acc[mt][nt][3];
            if (act) {
                v0 = fmaxf(v0, 0.f); v1 = fmaxf(v1, 0.f);
                v2 = fmaxf(v2, 0.f); v3 = fmaxf(v3, 0.f);
            }
            if (r0 < M) *(float2*)(C + (size_t)r0 * NCH + c0) = make_float2(v0, v1);
            if (r0 + 8 < M) *(float2*)(C + (size_t)(r0 + 8) * NCH + c0) = make_float2(v2, v3);
        }
    }
}

// ---------------- fused edge kernel ----------------
// smem words: sM 16896 | sA 4608 | sB 4096 | sR 128 | sBias 128 | sSrc 128 | sDst 128
#define SMEM_EDGE_BYTES ((16896 + 4608 + 4096 + 128 + 128 + 128 + 128) * 4)
#define SM_STRIDE 132

__global__ void __launch_bounds__(256, 2)
edge_kernel(const void* __restrict__ ei_raw, const float* __restrict__ eattr,
            const float* __restrict__ xpos, const float* __restrict__ h,
            float* __restrict__ agg, const unsigned* __restrict__ wpack,
            const float* __restrict__ mb1, const float* __restrict__ mb2,
            const float* __restrict__ mb3, int E) {
    extern __shared__ float smem[];
    unsigned* sM = (unsigned*)smem;            // 128 x 132 (inter-stage A / final m)
    unsigned* sA = sM + 16896;                 // 128 x 36 (stage-1 A chunk)
    unsigned* sB = sA + 4608;                  // 4096 (packed weight chunk)
    float* sR = (float*)(sB + 4096);           // 128
    float* sBias = sR + 128;                   // 128
    int* sSrc = (int*)(sBias + 128);
    int* sDst = sSrc + 128;

    const int tid = threadIdx.x;
    const int lane = tid & 31;
    const int warp = tid >> 5;
    const int wm = warp >> 2, wn = warp & 3;
    const int e0 = blockIdx.x * 128;
    const int is64 = g_is64;

    // prologue: indices, radial distance, stage-1 bias
    if (tid < 128) {
        int e = e0 + tid;
        int s = 0, d = -1;
        float r = 0.f;
        if (e < E) {
            if (is64) {
                const long long* p = (const long long*)ei_raw;
                s = (int)p[e];
                d = (int)p[(size_t)E + e];
            } else {
                const int* p = (const int*)ei_raw;
                s = p[e];
                d = p[(size_t)E + e];
            }
            float dx = xpos[3 * d + 0] - xpos[3 * s + 0];
            float dy = xpos[3 * d + 1] - xpos[3 * s + 1];
            float dz = xpos[3 * d + 2] - xpos[3 * s + 2];
            r = sqrtf(dx * dx + dy * dy + dz * dz);
        }
        sSrc[tid] = s;
        sDst[tid] = d;
        sR[tid] = r;
        sBias[tid] = mb1[tid];
    }
    __syncthreads();

    float acc[4][4][4];
    init_acc(acc, sBias, wn, lane);

    // ---------------- stage 1: [128 x 288] @ mw1 + mb1, gelu ----------------
#pragma unroll 1
    for (int kc = 0; kc < 9; kc++) {
        if (kc == 0) {
            // sin/cos features (cols 0..15 sin, 16..31 cos) via sincosf
            const float INV2PI = 0.15915494309189535f;
            const float CA = 6.2831854820251465f;
            const float CB = -1.7484555e-7f;
#pragma unroll
            for (int i = 0; i < 8; i++) {
                int lin = tid + i * 256;
                int row = lin >> 4, j = lin & 15;
                float omega = 10.f * exp2f(7.f - 0.875f * (float)j);
                float x = sR[row] * omega;
                float n = rintf(x * INV2PI);
                float rr = fmaf(-n, CA, x);
                rr = fmaf(-n, CB, rr);
                float sv, cv;
                sincosf(rr, &sv, &cv);
                sA[row * 36 + j] = f2tf(sv);
                sA[row * 36 + 16 + j] = f2tf(cv);
            }
        } else if (kc <= 4) {
            // edge_attr cols (32..159): LDG128 -> convert -> STS128 (conflict-free)
#pragma unroll
            for (int i = 0; i < 4; i++) {
                int lin = tid + i * 256;
                int row = lin >> 3, c4 = lin & 7;
                float4 v = make_float4(0.f, 0.f, 0.f, 0.f);
                int e = e0 + row;
                if (e < E)
                    v = *(const float4*)(eattr + (size_t)e * NCH + (kc - 1) * 32 + c4 * 4);
                uint4 u;
                u.x = f2tf(v.x); u.y = f2tf(v.y); u.z = f2tf(v.z); u.w = f2tf(v.w);
                *(uint4*)&sA[row * 36 + c4 * 4] = u;
            }
        } else {
            // h[src] gather (cols 160..287)
#pragma unroll
            for (int i = 0; i < 4; i++) {
                int lin = tid + i * 256;
                int row = lin >> 3, c4 = lin & 7;
                int s = sSrc[row];
                float4 v = *(const float4*)(h + (size_t)s * NCH + (kc - 5) * 32 + c4 * 4);
                uint4 u;
                u.x = f2tf(v.x); u.y = f2tf(v.y); u.z = f2tf(v.z); u.w = f2tf(v.w);
                *(uint4*)&sA[row * 36 + c4 * 4] = u;
            }
        }
        // weight chunk: pre-packed, pre-converted -> pure copy
        const uint4* bs = (const uint4*)(wpack + OFF_MW1 + (size_t)kc * 4096);
#pragma unroll
        for (int i = 0; i < 4; i++)
            ((uint4*)sB)[tid + i * 256] = bs[tid + i * 256];
        __syncthreads();
        mma_chunk_rm(acc, sA, 36, 0, sB, wm, wn, lane);
        __syncthreads();
    }
    epi_tf32_gelu(acc, sM, SM_STRIDE, wm, wn, lane);
    if (tid < 128) sBias[tid] = mb2[tid];
    __syncthreads();

    // ---------------- stage 2: K=128, A resident in sM ----------------
    init_acc(acc, sBias, wn, lane);
#pragma unroll 1
    for (int kc = 0; kc < 4; kc++) {
        const uint4* bs = (const uint4*)(wpack + OFF_MW2 + (size_t)kc * 4096);
#pragma unroll
        for (int i = 0; i < 4; i++)
            ((uint4*)sB)[tid + i * 256] = bs[tid + i * 256];
        __syncthreads();
        mma_chunk_rm(acc, sM, SM_STRIDE, kc * 32, sB, wm, wn, lane);
        __syncthreads();
    }
    epi_tf32_gelu(acc, sM, SM_STRIDE, wm, wn, lane);
    if (tid < 128) sBias[tid] = mb3[tid];
    __syncthreads();

    // ---------------- stage 3: K=128, no gelu ----------------
    init_acc(acc, sBias, wn, lane);
#pragma unroll 1
    for (int kc = 0; kc < 4; kc++) {
        const uint4* bs = (const uint4*)(wpack + OFF_MW3 + (size_t)kc * 4096);
#pragma unroll
        for (int i = 0; i < 4; i++)
            ((uint4*)sB)[tid + i * 256] = bs[tid + i * 256];
        __syncthreads();
        mma_chunk_rm(acc, sM, SM_STRIDE, kc * 32, sB, wm, wn, lane);
        __syncthreads();
    }
    // stage-3 epilogue: fp32 row-major into sM, then scatter
    float* sMf = (float*)sM;
#pragma unroll
    for (int mt = 0; mt < 4; mt++) {
        int r0 = wm * 64 + mt * 16 + (lane >> 2);
#pragma unroll
        for (int nt = 0; nt < 4; nt++) {
            int c0 = wn * 32 + nt * 8 + (lane & 3) * 2;
            *(float2*)&sMf[r0 * SM_STRIDE + c0] = make_float2(acc[mt][nt][0], acc[mt][nt][1]);
            *(float2*)&sMf[(r0 + 8) * SM_STRIDE + c0] = make_float2(acc[mt][nt][2], acc[mt][nt][3]);
        }
    }
    __syncthreads();

    // ---------------- scatter: agg[dst] += m ----------------
#pragma unroll
    for (int i = 0; i < 16; i++) {
        int lin = tid + i * 256;
        int row = lin >> 5, c4 = lin & 31;
        int d = sDst[row];
        if (d >= 0) {
            float4 v = *(float4*)&sMf[row * SM_STRIDE + c4 * 4];
            float* p = agg + (size_t)d * NCH + c4 * 4;
            asm volatile("red.global.add.v4.f32 [%0], {%1,%2,%3,%4};" ::
                             "l"(p), "f"(v.x), "f"(v.y), "f"(v.z), "f"(v.w)
                         : "memory");
        }
    }
}

// ---------------- launch ----------------
extern "C" void kernel_launch(void* const* d_in, const int* in_sizes, int n_in,
                              void* d_out, int out_size) {
    const float* x     = (const float*)d_in[0];
    const void*  ei    = d_in[1];
    const float* eattr = (const float*)d_in[2];
    const float* xpos  = (const float*)d_in[3];
    const float* w1  = (const float*)d_in[4];
    const float* b1  = (const float*)d_in[5];
    const float* mw1 = (const float*)d_in[6];
    const float* mb1 = (const float*)d_in[7];
    const float* mw2 = (const float*)d_in[8];
    const float* mb2 = (const float*)d_in[9];
    const float* mw3 = (const float*)d_in[10];
    const float* mb3 = (const float*)d_in[11];
    const float* w2  = (const float*)d_in[12];
    const float* b2  = (const float*)d_in[13];
    const float* w3  = (const float*)d_in[14];
    const float* b3  = (const float*)d_in[15];

    int N = in_sizes[0] / NCH;
    int E = in_sizes[1] / 2;
    float* out = (float*)d_out;

    float *hptr, *aptr, *tptr;
    unsigned* wp;
    cudaGetSymbolAddress((void**)&hptr, g_h);
    cudaGetSymbolAddress((void**)&aptr, g_agg);
    cudaGetSymbolAddress((void**)&tptr, g_t);
    cudaGetSymbolAddress((void**)&wp, g_wpack);

    cudaFuncSetAttribute(edge_kernel, cudaFuncAttributeMaxDynamicSharedMemorySize,
                         SMEM_EDGE_BYTES);

    detect_kernel<<<1, 1>>>(ei);

    // pre-pack weights into tf32 fragment layout
    pack_w<<<(36864 + 255) / 256, 256>>>(mw1, wp + OFF_MW1, 36864);
    pack_w<<<(16384 + 255) / 256, 256>>>(mw2, wp + OFF_MW2, 16384);
    pack_w<<<(16384 + 255) / 256, 256>>>(mw3, wp + OFF_MW3, 16384);
    pack_w<<<(16384 + 255) / 256, 256>>>(w1, wp + OFF_W1, 16384);
    pack_w<<<(16384 + 255) / 256, 256>>>(w2, wp + OFF_W2, 16384);
    pack_w<<<(16384 + 255) / 256, 256>>>(w3, wp + OFF_W3, 16384);

    int n4 = N * NCH / 4;
    zero_kernel<<<(n4 + 255) / 256, 256>>>((float4*)aptr, n4);

    node_gemm<<<(N + 127) / 128, 256>>>(x, nullptr, wp + OFF_W1, b1, hptr, N, 0);

    edge_kernel<<<(E + 127) / 128, 256, SMEM_EDGE_BYTES>>>(
        ei, eattr, xpos, hptr, aptr, wp, mb1, mb2, mb3, E);

    node_gemm<<<(N + 127) / 128, 256>>>(hptr, aptr, wp + OFF_W2, b2, tptr, N, 1);
    node_gemm<<<(N + 127) / 128, 256>>>(tptr, nullptr, wp + OFF_W3, b3, out, N, 0);
}

// round 4
// speedup vs baseline: 3.6971x; 1.2573x over previous
#include <cuda_runtime.h>
#include <cstdint>
#include <cstddef>

#define NCH 128
#define MAXN 50000

// ---------------- scratch ----------------
__device__ float    g_h[(size_t)MAXN * NCH];
__device__ unsigned g_htf[(size_t)MAXN * NCH];   // tf32 copy of h for edge gather
__device__ float    g_agg[(size_t)MAXN * NCH];
__device__ float    g_t[(size_t)MAXN * NCH];
__device__ unsigned g_wpack[118784];
__device__ int      g_is64;

#define OFF_MW1 0
#define OFF_MW2 36864
#define OFF_MW3 53248
#define OFF_W1  69632
#define OFF_W2  86016
#define OFF_W3  102400

// ---------------- helpers ----------------
__device__ __forceinline__ unsigned f2tf(float f) {
    unsigned u;
    asm("cvt.rna.tf32.f32 %0, %1;" : "=r"(u) : "f"(f));
    return u;
}

__device__ __forceinline__ void mma8(float c[4],
                                     unsigned a0, unsigned a1, unsigned a2, unsigned a3,
                                     unsigned b0, unsigned b1) {
    asm volatile(
        "mma.sync.aligned.m16n8k8.row.col.f32.tf32.tf32.f32 "
        "{%0,%1,%2,%3},{%4,%5,%6,%7},{%8,%9},{%0,%1,%2,%3};\n"
        : "+f"(c[0]), "+f"(c[1]), "+f"(c[2]), "+f"(c[3])
        : "r"(a0), "r"(a1), "r"(a2), "r"(a3), "r"(b0), "r"(b1));
}

__device__ __forceinline__ float gelu_exact(float x) {
    return 0.5f * x * (1.0f + erff(x * 0.70710678118654752f));
}

// cp.async
__device__ __forceinline__ void cpa16(unsigned dst, const void* src, int srcsize) {
    asm volatile("cp.async.cg.shared.global [%0], [%1], 16, %2;\n"
                 :: "r"(dst), "l"(src), "r"(srcsize) : "memory");
}
__device__ __forceinline__ void cpa_commit() {
    asm volatile("cp.async.commit_group;\n" ::: "memory");
}
__device__ __forceinline__ void cpa_wait1() {
    asm volatile("cp.async.wait_group 1;\n" ::: "memory");
}
__device__ __forceinline__ void cpa_wait0() {
    asm volatile("cp.async.wait_group 0;\n" ::: "memory");
}

// ---------------- mainloop: one K=32 chunk ----------------
__device__ __forceinline__ void mma_chunk_rm(float acc[4][4][4],
                                             const unsigned* __restrict__ sA, int stride, int kbase,
                                             const unsigned* __restrict__ sB,
                                             int wm, int wn, int lane) {
    const uint2* B2 = (const uint2*)sB;
#pragma unroll
    for (int kk = 0; kk < 4; kk++) {
        uint2 bf[4];
#pragma unroll
        for (int nt = 0; nt < 4; nt++)
            bf[nt] = B2[(kk * 16 + wn * 4 + nt) * 32 + lane];
#pragma unroll
        for (int mt = 0; mt < 4; mt++) {
            const unsigned* ap = sA + (wm * 64 + mt * 16 + (lane >> 2)) * stride
                                 + kbase + kk * 8 + (lane & 3);
            unsigned a0 = ap[0];
            unsigned a1 = ap[8 * stride];
            unsigned a2 = ap[4];
            unsigned a3 = ap[8 * stride + 4];
#pragma unroll
            for (int nt = 0; nt < 4; nt++)
                mma8(acc[mt][nt], a0, a1, a2, a3, bf[nt].x, bf[nt].y);
        }
    }
}

__device__ __forceinline__ void init_acc(float acc[4][4][4], const float* sBias, int wn, int lane) {
#pragma unroll
    for (int nt = 0; nt < 4; nt++) {
        int c = wn * 32 + nt * 8 + (lane & 3) * 2;
        float x0 = sBias[c], x1 = sBias[c + 1];
#pragma unroll
        for (int mt = 0; mt < 4; mt++) {
            acc[mt][nt][0] = x0; acc[mt][nt][1] = x1;
            acc[mt][nt][2] = x0; acc[mt][nt][3] = x1;
        }
    }
}

__device__ __forceinline__ void epi_tf32_gelu(float acc[4][4][4], unsigned* sM, int stride,
                                              int wm, int wn, int lane) {
#pragma unroll
    for (int mt = 0; mt < 4; mt++) {
        int r0 = wm * 64 + mt * 16 + (lane >> 2);
#pragma unroll
        for (int nt = 0; nt < 4; nt++) {
            int c0 = wn * 32 + nt * 8 + (lane & 3) * 2;
            uint2 u0, u1;
            u0.x = f2tf(gelu_exact(acc[mt][nt][0]));
            u0.y = f2tf(gelu_exact(acc[mt][nt][1]));
            u1.x = f2tf(gelu_exact(acc[mt][nt][2]));
            u1.y = f2tf(gelu_exact(acc[mt][nt][3]));
            *(uint2*)&sM[r0 * stride + c0] = u0;
            *(uint2*)&sM[(r0 + 8) * stride + c0] = u1;
        }
    }
}

// ---------------- misc kernels ----------------
__global__ void zero_kernel(float4* p, int n4) {
    int i = blockIdx.x * blockDim.x + threadIdx.x;
    if (i < n4) p[i] = make_float4(0.f, 0.f, 0.f, 0.f);
}

__global__ void detect_kernel(const void* ei) {
    const long long* p = (const long long*)ei;
    bool is64 = true;
    for (int i = 0; i < 8; i++) {
        long long v = p[i];
        if (v < 0 || v >= (1LL << 31)) is64 = false;
    }
    g_is64 = is64 ? 1 : 0;
}

// pack three [K x 128] weights into tf32 fragment order
__global__ void pack3(const float* __restrict__ s0, unsigned* __restrict__ d0, int n0,
                      const float* __restrict__ s1, unsigned* __restrict__ d1, int n1,
                      const float* __restrict__ s2, unsigned* __restrict__ d2, int n2) {
    int idx = blockIdx.x * blockDim.x + threadIdx.x;
    const float* s; unsigned* d; int loc;
    if (idx < n0) { s = s0; d = d0; loc = idx; }
    else if (idx < n0 + n1) { s = s1; d = d1; loc = idx - n0; }
    else if (idx < n0 + n1 + n2) { s = s2; d = d2; loc = idx - n0 - n1; }
    else return;
    int e = loc & 1;
    int lane = (loc >> 1) & 31;
    int u = (loc >> 6) & 15;
    int kk = (loc >> 10) & 3;
    int kc = loc >> 12;
    int k = kc * 32 + kk * 8 + e * 4 + (lane & 3);
    int n = u * 8 + (lane >> 2);
    d[loc] = f2tf(s[(size_t)k * NCH + n]);
}

// ---------------- tf32 node GEMM ----------------
__global__ void __launch_bounds__(256, 2)
node_gemm(const float* __restrict__ A, const float* __restrict__ A2,
          const unsigned* __restrict__ Wp, const float* __restrict__ bias,
          float* __restrict__ C, unsigned* __restrict__ Ctf, int M, int act) {
    __shared__ __align__(16) unsigned sA[128 * 36];
    __shared__ __align__(16) unsigned sB[4096];
    __shared__ float sBias[128];
    const int tid = threadIdx.x;
    const int lane = tid & 31;
    const int warp = tid >> 5;
    const int wm = warp >> 2, wn = warp & 3;
    const int m0 = blockIdx.x * 128;

    if (tid < 128) sBias[tid] = bias[tid];
    __syncthreads();

    float acc[4][4][4];
    init_acc(acc, sBias, wn, lane);

#pragma unroll 1
    for (int kc = 0; kc < 4; kc++) {
#pragma unroll
        for (int i = 0; i < 4; i++) {
            int lin = tid + i * 256;
            int row = lin >> 3, c4 = lin & 7;
            float4 v = make_float4(0.f, 0.f, 0.f, 0.f);
            if (m0 + row < M) {
                v = *(const float4*)(A + (size_t)(m0 + row) * NCH + kc * 32 + c4 * 4);
                if (A2) {
                    float4 w = *(const float4*)(A2 + (size_t)(m0 + row) * NCH + kc * 32 + c4 * 4);
                    v.x += w.x; v.y += w.y; v.z += w.z; v.w += w.w;
                }
            }
            uint4 u;
            u.x = f2tf(v.x); u.y = f2tf(v.y); u.z = f2tf(v.z); u.w = f2tf(v.w);
            *(uint4*)&sA[row * 36 + c4 * 4] = u;
        }
        const uint4* bs = (const uint4*)(Wp + (size_t)kc * 4096);
#pragma unroll
        for (int i = 0; i < 4; i++)
            ((uint4*)sB)[tid + i * 256] = bs[tid + i * 256];
        __syncthreads();
        mma_chunk_rm(acc, sA, 36, 0, sB, wm, wn, lane);
        __syncthreads();
    }

#pragma unroll
    for (int mt = 0; mt < 4; mt++) {
        int r0 = m0 + wm * 64 + mt * 16 + (lane >> 2);
#pragma unroll
        for (int nt = 0; nt < 4; nt++) {
            int c0 = wn * 32 + nt * 8 + (lane & 3) * 2;
            float v0 = acc[mt][nt][0], v1 = acc[mt][nt][1];
            float v2 = acc[mt][nt][2], v3 = acc[mt][nt][3];
            if (act) {
                v0 = fmaxf(v0, 0.f); v1 = fmaxf(v1, 0.f);
                v2 = fmaxf(v2, 0.f); v3 = fmaxf(v3, 0.f);
            }
            if (r0 < M) {
                *(float2*)(C + (size_t)r0 * NCH + c0) = make_float2(v0, v1);
                if (Ctf) {
                    uint2 u; u.x = f2tf(v0); u.y = f2tf(v1);
                    *(uint2*)(Ctf + (size_t)r0 * NCH + c0) = u;
                }
            }
            if (r0 + 8 < M) {
                *(float2*)(C + (size_t)(r0 + 8) * NCH + c0) = make_float2(v2, v3);
                if (Ctf) {
                    uint2 u; u.x = f2tf(v2); u.y = f2tf(v3);
                    *(uint2*)(Ctf + (size_t)(r0 + 8) * NCH + c0) = u;
                }
            }
        }
    }
}

// ---------------- fused edge kernel (cp.async pipelined) ----------------
// smem words: sM 16896 (holds A dbl-buffers in stage1, then inter-stage/out)
//             sB 2x4096 | sR 128 | sBiasAll 384 | sSrc 128 | sDst 128
#define SMEM_WORDS (16896 + 8192 + 128 + 384 + 128 + 128)
#define SMEM_EDGE_BYTES (SMEM_WORDS * 4)
#define SM_STRIDE 132
#define SA_STRIDE 36
#define SA_BUF 4608

__device__ __forceinline__ const unsigned* chunk_src(const unsigned* wpack, int g) {
    if (g < 9)  return wpack + OFF_MW1 + (size_t)g * 4096;
    if (g < 13) return wpack + OFF_MW2 + (size_t)(g - 9) * 4096;
    return wpack + OFF_MW3 + (size_t)(g - 13) * 4096;
}

__global__ void __launch_bounds__(256, 2)
edge_kernel(const void* __restrict__ ei_raw, const float* __restrict__ eattr,
            const float* __restrict__ xpos, const unsigned* __restrict__ htf,
            float* __restrict__ agg, const unsigned* __restrict__ wpack,
            const float* __restrict__ mb1, const float* __restrict__ mb2,
            const float* __restrict__ mb3, int E) {
    extern __shared__ float smem[];
    unsigned* sM = (unsigned*)smem;              // 16896
    unsigned* sB0 = sM + 16896;                  // 4096
    unsigned* sB1 = sB0 + 4096;                  // 4096
    float* sR = (float*)(sB1 + 4096);            // 128
    float* sBiasAll = sR + 128;                  // 384
    int* sSrc = (int*)(sBiasAll + 384);          // 128
    int* sDst = sSrc + 128;                      // 128

    const unsigned smem_u32 = (unsigned)__cvta_generic_to_shared(smem);
    const unsigned sB_b[2] = { smem_u32 + 16896u * 4u, smem_u32 + (16896u + 4096u) * 4u };
    const unsigned sA_b[2] = { smem_u32, smem_u32 + (unsigned)SA_BUF * 4u };

    const int tid = threadIdx.x;
    const int lane = tid & 31;
    const int warp = tid >> 5;
    const int wm = warp >> 2, wn = warp & 3;
    const int e0 = blockIdx.x * 128;
    const int is64 = g_is64;

    // prologue: indices, distance, biases
    if (tid < 128) {
        int e = e0 + tid;
        int s = 0, d = -1;
        float r = 0.f;
        if (e < E) {
            if (is64) {
                const long long* p = (const long long*)ei_raw;
                s = (int)p[e];
                d = (int)p[(size_t)E + e];
            } else {
                const int* p = (const int*)ei_raw;
                s = p[e];
                d = p[(size_t)E + e];
            }
            float dx = xpos[3 * d + 0] - xpos[3 * s + 0];
            float dy = xpos[3 * d + 1] - xpos[3 * s + 1];
            float dz = xpos[3 * d + 2] - xpos[3 * s + 2];
            r = sqrtf(dx * dx + dy * dy + dz * dz);
        }
        sSrc[tid] = s;
        sDst[tid] = d;
        sR[tid] = r;
        sBiasAll[tid] = mb1[tid];
        sBiasAll[128 + tid] = mb2[tid];
        sBiasAll[256 + tid] = mb3[tid];
    }
    __syncthreads();

    // features (stage-1 chunk 0 A) into sA buf0
    {
        const float INV2PI = 0.15915494309189535f;
        const float CA = 6.2831854820251465f;
        const float CB = -1.7484555e-7f;
        unsigned* sA0 = sM;
#pragma unroll
        for (int i = 0; i < 8; i++) {
            int lin = tid + i * 256;
            int row = lin >> 4, j = lin & 15;
            float omega = 10.f * exp2f(7.f - 0.875f * (float)j);
            float x = sR[row] * omega;
            float n = rintf(x * INV2PI);
            float rr = fmaf(-n, CA, x);
            rr = fmaf(-n, CB, rr);
            float sv, cv;
            sincosf(rr, &sv, &cv);
            sA0[row * SA_STRIDE + j] = f2tf(sv);
            sA0[row * SA_STRIDE + 16 + j] = f2tf(cv);
        }
    }

    // prefetch B chunk 0
#pragma unroll
    for (int i = 0; i < 4; i++) {
        int q = tid + i * 256;
        cpa16(sB_b[0] + q * 16, chunk_src(wpack, 0) + q * 4, 16);
    }
    cpa_commit();

    float acc[4][4][4];
    init_acc(acc, sBiasAll, wn, lane);

    // ---------------- stage 1: 9 chunks (K=288) ----------------
#pragma unroll 1
    for (int kc = 0; kc < 9; kc++) {
        __syncthreads();  // buf[(kc+1)&1] free
        if (kc < 8) {
            int g = kc + 1;
            // A for chunk g
#pragma unroll
            for (int i = 0; i < 4; i++) {
                int lin = tid + i * 256;
                int row = lin >> 3, c4 = lin & 7;
                unsigned dst = sA_b[g & 1] + (unsigned)(row * SA_STRIDE + c4 * 4) * 4u;
                if (g < 5) {
                    int e = e0 + row;
                    const float* src = eattr + ((e < E) ? ((size_t)e * NCH + (g - 1) * 32 + c4 * 4) : 0);
                    cpa16(dst, src, (e < E) ? 16 : 0);
                } else {
                    const unsigned* src = htf + (size_t)sSrc[row] * NCH + (g - 5) * 32 + c4 * 4;
                    cpa16(dst, src, 16);
                }
            }
            // B for chunk g
            const unsigned* bs = chunk_src(wpack, g);
#pragma unroll
            for (int i = 0; i < 4; i++) {
                int q = tid + i * 256;
                cpa16(sB_b[g & 1] + q * 16, bs + q * 4, 16);
            }
            cpa_commit();
            cpa_wait1();
        } else {
            cpa_wait0();
        }
        __syncthreads();  // chunk kc visible
        mma_chunk_rm(acc, sM + (kc & 1) * SA_BUF, SA_STRIDE, 0, (kc & 1) ? sB1 : sB0, wm, wn, lane);
    }

    // ---------------- boundary 1->2 ----------------
    __syncthreads();  // all stage-1 MMAs done; sA region dead
    {
        const unsigned* bs = chunk_src(wpack, 9);
#pragma unroll
        for (int i = 0; i < 4; i++) {
            int q = tid + i * 256;
            cpa16(sB_b[0] + q * 16, bs + q * 4, 16);
        }
        cpa_commit();
    }
    epi_tf32_gelu(acc, sM, SM_STRIDE, wm, wn, lane);
    init_acc(acc, sBiasAll + 128, wn, lane);

    // ---------------- stage 2: 4 chunks ----------------
#pragma unroll 1
    for (int kc = 0; kc < 4; kc++) {
        __syncthreads();
        if (kc < 3) {
            const unsigned* bs = chunk_src(wpack, 10 + kc);
#pragma unroll
            for (int i = 0; i < 4; i++) {
                int q = tid + i * 256;
                cpa16(sB_b[(kc + 1) & 1] + q * 16, bs + q * 4, 16);
            }
            cpa_commit();
            cpa_wait1();
        } else {
            cpa_wait0();
        }
        __syncthreads();
        mma_chunk_rm(acc, sM, SM_STRIDE, kc * 32, (kc & 1) ? sB1 : sB0, wm, wn, lane);
    }

    // ---------------- boundary 2->3 ----------------
    __syncthreads();
    {
        const unsigned* bs = chunk_src(wpack, 13);
#pragma unroll
        for (int i = 0; i < 4; i++) {
            int q = tid + i * 256;
            cpa16(sB_b[0] + q * 16, bs + q * 4, 16);
        }
        cpa_commit();
    }
    epi_tf32_gelu(acc, sM, SM_STRIDE, wm, wn, lane);
    init_acc(acc, sBiasAll + 256, wn, lane);

    // ---------------- stage 3: 4 chunks ----------------
#pragma unroll 1
    for (int kc = 0; kc < 4; kc++) {
        __syncthreads();
        if (kc < 3) {
            const unsigned* bs = chunk_src(wpack, 14 + kc);
#pragma unroll
            for (int i = 0; i < 4; i++) {
                int q = tid + i * 256;
                cpa16(sB_b[(kc + 1) & 1] + q * 16, bs + q * 4, 16);
            }
            cpa_commit();
            cpa_wait1();
        } else {
            cpa_wait0();
        }
        __syncthreads();
        mma_chunk_rm(acc, sM, SM_STRIDE, kc * 32, (kc & 1) ? sB1 : sB0, wm, wn, lane);
    }
    __syncthreads();  // all stage-3 MMAs done before overwriting sM

    // stage-3 epilogue: fp32 row-major into sM
    float* sMf = (float*)sM;
#pragma unroll
    for (int mt = 0; mt < 4; mt++) {
        int r0 = wm * 64 + mt * 16 + (lane >> 2);
#pragma unroll
        for (int nt = 0; nt < 4; nt++) {
            int c0 = wn * 32 + nt * 8 + (lane & 3) * 2;
            *(float2*)&sMf[r0 * SM_STRIDE + c0] = make_float2(acc[mt][nt][0], acc[mt][nt][1]);
            *(float2*)&sMf[(r0 + 8) * SM_STRIDE + c0] = make_float2(acc[mt][nt][2], acc[mt][nt][3]);
        }
    }
    __syncthreads();

    // scatter: agg[dst] += m
#pragma unroll
    for (int i = 0; i < 16; i++) {
        int lin = tid + i * 256;
        int row = lin >> 5, c4 = lin & 31;
        int d = sDst[row];
        if (d >= 0) {
            float4 v = *(float4*)&sMf[row * SM_STRIDE + c4 * 4];
            float* p = agg + (size_t)d * NCH + c4 * 4;
            asm volatile("red.global.add.v4.f32 [%0], {%1,%2,%3,%4};" ::
                             "l"(p), "f"(v.x), "f"(v.y), "f"(v.z), "f"(v.w)
                         : "memory");
        }
    }
}

// ---------------- launch ----------------
extern "C" void kernel_launch(void* const* d_in, const int* in_sizes, int n_in,
                              void* d_out, int out_size) {
    const float* x     = (const float*)d_in[0];
    const void*  ei    = d_in[1];
    const float* eattr = (const float*)d_in[2];
    const float* xpos  = (const float*)d_in[3];
    const float* w1  = (const float*)d_in[4];
    const float* b1  = (const float*)d_in[5];
    const float* mw1 = (const float*)d_in[6];
    const float* mb1 = (const float*)d_in[7];
    const float* mw2 = (const float*)d_in[8];
    const float* mb2 = (const float*)d_in[9];
    const float* mw3 = (const float*)d_in[10];
    const float* mb3 = (const float*)d_in[11];
    const float* w2  = (const float*)d_in[12];
    const float* b2  = (const float*)d_in[13];
    const float* w3  = (const float*)d_in[14];
    const float* b3  = (const float*)d_in[15];

    int N = in_sizes[0] / NCH;
    int E = in_sizes[1] / 2;
    float* out = (float*)d_out;

    float *hptr, *aptr, *tptr;
    unsigned *wp, *htf;
    cudaGetSymbolAddress((void**)&hptr, g_h);
    cudaGetSymbolAddress((void**)&aptr, g_agg);
    cudaGetSymbolAddress((void**)&tptr, g_t);
    cudaGetSymbolAddress((void**)&wp, g_wpack);
    cudaGetSymbolAddress((void**)&htf, g_htf);

    cudaFuncSetAttribute(edge_kernel, cudaFuncAttributeMaxDynamicSharedMemorySize,
                         SMEM_EDGE_BYTES);

    // launch 1
    detect_kernel<<<1, 1>>>(ei);
    // launch 2
    pack3<<<(36864 + 16384 + 16384 + 255) / 256, 256>>>(
        mw1, wp + OFF_MW1, 36864, mw2, wp + OFF_MW2, 16384, mw3, wp + OFF_MW3, 16384);
    // launch 3
    pack3<<<(3 * 16384 + 255) / 256, 256>>>(
        w1, wp + OFF_W1, 16384, w2, wp + OFF_W2, 16384, w3, wp + OFF_W3, 16384);
    // launch 4
    int n4 = N * NCH / 4;
    zero_kernel<<<(n4 + 255) / 256, 256>>>((float4*)aptr, n4);
    // launch 5
    node_gemm<<<(N + 127) / 128, 256>>>(x, nullptr, wp + OFF_W1, b1, hptr, htf, N, 0);
    // launch 6 (ncu -s 5 -c 1 captures this one)
    edge_kernel<<<(E + 127) / 128, 256, SMEM_EDGE_BYTES>>>(
        ei, eattr, xpos, htf, aptr, wp, mb1, mb2, mb3, E);
    // launch 7
    node_gemm<<<(N + 127) / 128, 256>>>(hptr, aptr, wp + OFF_W2, b2, tptr, nullptr, N, 1);
    // launch 8
    node_gemm<<<(N + 127) / 128, 256>>>(tptr, nullptr, wp + OFF_W3, b3, out, nullptr, N, 0);
}

// round 5
// speedup vs baseline: 3.7043x; 1.0019x over previous
#include <cuda_runtime.h>
#include <cstdint>
#include <cstddef>

#define NCH 128
#define MAXN 50000

// ---------------- scratch ----------------
__device__ float    g_h[(size_t)MAXN * NCH];
__device__ unsigned g_htf[(size_t)MAXN * NCH];   // tf32 copy of h for edge gather
__device__ float    g_agg[(size_t)MAXN * NCH];
__device__ float    g_t[(size_t)MAXN * NCH];
__device__ unsigned g_wpack[118784];
__device__ int      g_is64;

#define OFF_MW1 0
#define OFF_MW2 36864
#define OFF_MW3 53248
#define OFF_W1  69632
#define OFF_W2  86016
#define OFF_W3  102400

// ---------------- helpers ----------------
__device__ __forceinline__ unsigned f2tf(float f) {
    unsigned u;
    asm("cvt.rna.tf32.f32 %0, %1;" : "=r"(u) : "f"(f));
    return u;
}

__device__ __forceinline__ void mma8(float c[4],
                                     unsigned a0, unsigned a1, unsigned a2, unsigned a3,
                                     unsigned b0, unsigned b1) {
    asm volatile(
        "mma.sync.aligned.m16n8k8.row.col.f32.tf32.tf32.f32 "
        "{%0,%1,%2,%3},{%4,%5,%6,%7},{%8,%9},{%0,%1,%2,%3};\n"
        : "+f"(c[0]), "+f"(c[1]), "+f"(c[2]), "+f"(c[3])
        : "r"(a0), "r"(a1), "r"(a2), "r"(a3), "r"(b0), "r"(b1));
}

__device__ __forceinline__ float gelu_exact(float x) {
    return 0.5f * x * (1.0f + erff(x * 0.70710678118654752f));
}

// cp.async
__device__ __forceinline__ void cpa16(unsigned dst, const void* src, int srcsize) {
    asm volatile("cp.async.cg.shared.global [%0], [%1], 16, %2;\n"
                 :: "r"(dst), "l"(src), "r"(srcsize) : "memory");
}
__device__ __forceinline__ void cpa_commit() {
    asm volatile("cp.async.commit_group;\n" ::: "memory");
}
__device__ __forceinline__ void cpa_wait1() {
    asm volatile("cp.async.wait_group 1;\n" ::: "memory");
}
__device__ __forceinline__ void cpa_wait0() {
    asm volatile("cp.async.wait_group 0;\n" ::: "memory");
}

// ---------------- mainloop: one K=32 chunk ----------------
__device__ __forceinline__ void mma_chunk_rm(float acc[4][4][4],
                                             const unsigned* __restrict__ sA, int stride, int kbase,
                                             const unsigned* __restrict__ sB,
                                             int wm, int wn, int lane) {
    const uint2* B2 = (const uint2*)sB;
#pragma unroll
    for (int kk = 0; kk < 4; kk++) {
        uint2 bf[4];
#pragma unroll
        for (int nt = 0; nt < 4; nt++)
            bf[nt] = B2[(kk * 16 + wn * 4 + nt) * 32 + lane];
#pragma unroll
        for (int mt = 0; mt < 4; mt++) {
            const unsigned* ap = sA + (wm * 64 + mt * 16 + (lane >> 2)) * stride
                                 + kbase + kk * 8 + (lane & 3);
            unsigned a0 = ap[0];
            unsigned a1 = ap[8 * stride];
            unsigned a2 = ap[4];
            unsigned a3 = ap[8 * stride + 4];
#pragma unroll
            for (int nt = 0; nt < 4; nt++)
                mma8(acc[mt][nt], a0, a1, a2, a3, bf[nt].x, bf[nt].y);
        }
    }
}

__device__ __forceinline__ void init_acc(float acc[4][4][4], const float* sBias, int wn, int lane) {
#pragma unroll
    for (int nt = 0; nt < 4; nt++) {
        int c = wn * 32 + nt * 8 + (lane & 3) * 2;
        float x0 = sBias[c], x1 = sBias[c + 1];
#pragma unroll
        for (int mt = 0; mt < 4; mt++) {
            acc[mt][nt][0] = x0; acc[mt][nt][1] = x1;
            acc[mt][nt][2] = x0; acc[mt][nt][3] = x1;
        }
    }
}

__device__ __forceinline__ void epi_tf32_gelu(float acc[4][4][4], unsigned* sM, int stride,
                                              int wm, int wn, int lane) {
#pragma unroll
    for (int mt = 0; mt < 4; mt++) {
        int r0 = wm * 64 + mt * 16 + (lane >> 2);
#pragma unroll
        for (int nt = 0; nt < 4; nt++) {
            int c0 = wn * 32 + nt * 8 + (lane & 3) * 2;
            uint2 u0, u1;
            u0.x = f2tf(gelu_exact(acc[mt][nt][0]));
            u0.y = f2tf(gelu_exact(acc[mt][nt][1]));
            u1.x = f2tf(gelu_exact(acc[mt][nt][2]));
            u1.y = f2tf(gelu_exact(acc[mt][nt][3]));
            *(uint2*)&sM[r0 * stride + c0] = u0;
            *(uint2*)&sM[(r0 + 8) * stride + c0] = u1;
        }
    }
}

// ---------------- misc kernels ----------------
__global__ void zero_kernel(float4* p, int n4) {
    int i = blockIdx.x * blockDim.x + threadIdx.x;
    if (i < n4) p[i] = make_float4(0.f, 0.f, 0.f, 0.f);
}

__global__ void detect_kernel(const void* ei) {
    const long long* p = (const long long*)ei;
    bool is64 = true;
    for (int i = 0; i < 8; i++) {
        long long v = p[i];
        if (v < 0 || v >= (1LL << 31)) is64 = false;
    }
    g_is64 = is64 ? 1 : 0;
}

// pack three [K x 128] weights into tf32 fragment order
__global__ void pack3(const float* __restrict__ s0, unsigned* __restrict__ d0, int n0,
                      const float* __restrict__ s1, unsigned* __restrict__ d1, int n1,
                      const float* __restrict__ s2, unsigned* __restrict__ d2, int n2) {
    int idx = blockIdx.x * blockDim.x + threadIdx.x;
    const float* s; unsigned* d; int loc;
    if (idx < n0) { s = s0; d = d0; loc = idx; }
    else if (idx < n0 + n1) { s = s1; d = d1; loc = idx - n0; }
    else if (idx < n0 + n1 + n2) { s = s2; d = d2; loc = idx - n0 - n1; }
    else return;
    int e = loc & 1;
    int lane = (loc >> 1) & 31;
    int u = (loc >> 6) & 15;
    int kk = (loc >> 10) & 3;
    int kc = loc >> 12;
    int k = kc * 32 + kk * 8 + e * 4 + (lane & 3);
    int n = u * 8 + (lane >> 2);
    d[loc] = f2tf(s[(size_t)k * NCH + n]);
}

// ---------------- tf32 node GEMM ----------------
__global__ void __launch_bounds__(256, 2)
node_gemm(const float* __restrict__ A, const float* __restrict__ A2,
          const unsigned* __restrict__ Wp, const float* __restrict__ bias,
          float* __restrict__ C, unsigned* __restrict__ Ctf, int M, int act) {
    __shared__ __align__(16) unsigned sA[128 * 36];
    __shared__ __align__(16) unsigned sB[4096];
    __shared__ float sBias[128];
    const int tid = threadIdx.x;
    const int lane = tid & 31;
    const int warp = tid >> 5;
    const int wm = warp >> 2, wn = warp & 3;
    const int m0 = blockIdx.x * 128;

    if (tid < 128) sBias[tid] = bias[tid];
    __syncthreads();

    float acc[4][4][4];
    init_acc(acc, sBias, wn, lane);

#pragma unroll 1
    for (int kc = 0; kc < 4; kc++) {
#pragma unroll
        for (int i = 0; i < 4; i++) {
            int lin = tid + i * 256;
            int row = lin >> 3, c4 = lin & 7;
            float4 v = make_float4(0.f, 0.f, 0.f, 0.f);
            if (m0 + row < M) {
                v = *(const float4*)(A + (size_t)(m0 + row) * NCH + kc * 32 + c4 * 4);
                if (A2) {
                    float4 w = *(const float4*)(A2 + (size_t)(m0 + row) * NCH + kc * 32 + c4 * 4);
                    v.x += w.x; v.y += w.y; v.z += w.z; v.w += w.w;
                }
            }
            uint4 u;
            u.x = f2tf(v.x); u.y = f2tf(v.y); u.z = f2tf(v.z); u.w = f2tf(v.w);
            *(uint4*)&sA[row * 36 + c4 * 4] = u;
        }
        const uint4* bs = (const uint4*)(Wp + (size_t)kc * 4096);
#pragma unroll
        for (int i = 0; i < 4; i++)
            ((uint4*)sB)[tid + i * 256] = bs[tid + i * 256];
        __syncthreads();
        mma_chunk_rm(acc, sA, 36, 0, sB, wm, wn, lane);
        __syncthreads();
    }

#pragma unroll
    for (int mt = 0; mt < 4; mt++) {
        int r0 = m0 + wm * 64 + mt * 16 + (lane >> 2);
#pragma unroll
        for (int nt = 0; nt < 4; nt++) {
            int c0 = wn * 32 + nt * 8 + (lane & 3) * 2;
            float v0 = acc[mt][nt][0], v1 = acc[mt][nt][1];
            float v2 = acc[mt][nt][2], v3 = acc[mt][nt][3];
            if (act) {
                v0 = fmaxf(v0, 0.f); v1 = fmaxf(v1, 0.f);
                v2 = fmaxf(v2, 0.f); v3 = fmaxf(v3, 0.f);
            }
            if (r0 < M) {
                *(float2*)(C + (size_t)r0 * NCH + c0) = make_float2(v0, v1);
                if (Ctf) {
                    uint2 u; u.x = f2tf(v0); u.y = f2tf(v1);
                    *(uint2*)(Ctf + (size_t)r0 * NCH + c0) = u;
                }
            }
            if (r0 + 8 < M) {
                *(float2*)(C + (size_t)(r0 + 8) * NCH + c0) = make_float2(v2, v3);
                if (Ctf) {
                    uint2 u; u.x = f2tf(v2); u.y = f2tf(v3);
                    *(uint2*)(Ctf + (size_t)(r0 + 8) * NCH + c0) = u;
                }
            }
        }
    }
}

// ---------------- fused edge kernel (cp.async pipelined) ----------------
// smem words: sM 16896 (holds A dbl-buffers in stage1, then inter-stage/out)
//             sB 2x4096 | sR 128 | sBiasAll 384 | sSrc 128 | sDst 128
#define SMEM_WORDS (16896 + 8192 + 128 + 384 + 128 + 128)
#define SMEM_EDGE_BYTES (SMEM_WORDS * 4)
#define SM_STRIDE 132
#define SA_STRIDE 36
#define SA_BUF 4608

__device__ __forceinline__ const unsigned* chunk_src(const unsigned* wpack, int g) {
    if (g < 9)  return wpack + OFF_MW1 + (size_t)g * 4096;
    if (g < 13) return wpack + OFF_MW2 + (size_t)(g - 9) * 4096;
    return wpack + OFF_MW3 + (size_t)(g - 13) * 4096;
}

__global__ void __launch_bounds__(256, 2)
edge_kernel(const void* __restrict__ ei_raw, const float* __restrict__ eattr,
            const float* __restrict__ xpos, const unsigned* __restrict__ htf,
            float* __restrict__ agg, const unsigned* __restrict__ wpack,
            const float* __restrict__ mb1, const float* __restrict__ mb2,
            const float* __restrict__ mb3, int E) {
    extern __shared__ float smem[];
    unsigned* sM = (unsigned*)smem;              // 16896
    unsigned* sB0 = sM + 16896;                  // 4096
    unsigned* sB1 = sB0 + 4096;                  // 4096
    float* sR = (float*)(sB1 + 4096);            // 128
    float* sBiasAll = sR + 128;                  // 384
    int* sSrc = (int*)(sBiasAll + 384);          // 128
    int* sDst = sSrc + 128;                      // 128

    const unsigned smem_u32 = (unsigned)__cvta_generic_to_shared(smem);
    const unsigned sB_b[2] = { smem_u32 + 16896u * 4u, smem_u32 + (16896u + 4096u) * 4u };
    const unsigned sA_b[2] = { smem_u32, smem_u32 + (unsigned)SA_BUF * 4u };

    const int tid = threadIdx.x;
    const int lane = tid & 31;
    const int warp = tid >> 5;
    const int wm = warp >> 2, wn = warp & 3;
    const int e0 = blockIdx.x * 128;
    const int is64 = g_is64;

    // prologue: indices, distance, biases
    if (tid < 128) {
        int e = e0 + tid;
        int s = 0, d = -1;
        float r = 0.f;
        if (e < E) {
            if (is64) {
                const long long* p = (const long long*)ei_raw;
                s = (int)p[e];
                d = (int)p[(size_t)E + e];
            } else {
                const int* p = (const int*)ei_raw;
                s = p[e];
                d = p[(size_t)E + e];
            }
            float dx = xpos[3 * d + 0] - xpos[3 * s + 0];
            float dy = xpos[3 * d + 1] - xpos[3 * s + 1];
            float dz = xpos[3 * d + 2] - xpos[3 * s + 2];
            r = sqrtf(dx * dx + dy * dy + dz * dz);
        }
        sSrc[tid] = s;
        sDst[tid] = d;
        sR[tid] = r;
        sBiasAll[tid] = mb1[tid];
        sBiasAll[128 + tid] = mb2[tid];
        sBiasAll[256 + tid] = mb3[tid];
    }
    __syncthreads();

    // features (stage-1 chunk 0 A) into sA buf0
    {
        const float INV2PI = 0.15915494309189535f;
        const float CA = 6.2831854820251465f;
        const float CB = -1.7484555e-7f;
        unsigned* sA0 = sM;
#pragma unroll
        for (int i = 0; i < 8; i++) {
            int lin = tid + i * 256;
            int row = lin >> 4, j = lin & 15;
            float omega = 10.f * exp2f(7.f - 0.875f * (float)j);
            float x = sR[row] * omega;
            float n = rintf(x * INV2PI);
            float rr = fmaf(-n, CA, x);
            rr = fmaf(-n, CB, rr);
            float sv, cv;
            sincosf(rr, &sv, &cv);
            sA0[row * SA_STRIDE + j] = f2tf(sv);
            sA0[row * SA_STRIDE + 16 + j] = f2tf(cv);
        }
    }

    // prefetch B chunk 0
#pragma unroll
    for (int i = 0; i < 4; i++) {
        int q = tid + i * 256;
        cpa16(sB_b[0] + q * 16, chunk_src(wpack, 0) + q * 4, 16);
    }
    cpa_commit();

    float acc[4][4][4];
    init_acc(acc, sBiasAll, wn, lane);

    // ---------------- stage 1: 9 chunks (K=288) ----------------
#pragma unroll 1
    for (int kc = 0; kc < 9; kc++) {
        __syncthreads();  // buf[(kc+1)&1] free
        if (kc < 8) {
            int g = kc + 1;
            // A for chunk g
#pragma unroll
            for (int i = 0; i < 4; i++) {
                int lin = tid + i * 256;
                int row = lin >> 3, c4 = lin & 7;
                unsigned dst = sA_b[g & 1] + (unsigned)(row * SA_STRIDE + c4 * 4) * 4u;
                if (g < 5) {
                    int e = e0 + row;
                    const float* src = eattr + ((e < E) ? ((size_t)e * NCH + (g - 1) * 32 + c4 * 4) : 0);
                    cpa16(dst, src, (e < E) ? 16 : 0);
                } else {
                    const unsigned* src = htf + (size_t)sSrc[row] * NCH + (g - 5) * 32 + c4 * 4;
                    cpa16(dst, src, 16);
                }
            }
            // B for chunk g
            const unsigned* bs = chunk_src(wpack, g);
#pragma unroll
            for (int i = 0; i < 4; i++) {
                int q = tid + i * 256;
                cpa16(sB_b[g & 1] + q * 16, bs + q * 4, 16);
            }
            cpa_commit();
            cpa_wait1();
        } else {
            cpa_wait0();
        }
        __syncthreads();  // chunk kc visible
        mma_chunk_rm(acc, sM + (kc & 1) * SA_BUF, SA_STRIDE, 0, (kc & 1) ? sB1 : sB0, wm, wn, lane);
    }

    // ---------------- boundary 1->2 ----------------
    __syncthreads();  // all stage-1 MMAs done; sA region dead
    {
        const unsigned* bs = chunk_src(wpack, 9);
#pragma unroll
        for (int i = 0; i < 4; i++) {
            int q = tid + i * 256;
            cpa16(sB_b[0] + q * 16, bs + q * 4, 16);
        }
        cpa_commit();
    }
    epi_tf32_gelu(acc, sM, SM_STRIDE, wm, wn, lane);
    init_acc(acc, sBiasAll + 128, wn, lane);

    // ---------------- stage 2: 4 chunks ----------------
#pragma unroll 1
    for (int kc = 0; kc < 4; kc++) {
        __syncthreads();
        if (kc < 3) {
            const unsigned* bs = chunk_src(wpack, 10 + kc);
#pragma unroll
            for (int i = 0; i < 4; i++) {
                int q = tid + i * 256;
                cpa16(sB_b[(kc + 1) & 1] + q * 16, bs + q * 4, 16);
            }
            cpa_commit();
            cpa_wait1();
        } else {
            cpa_wait0();
        }
        __syncthreads();
        mma_chunk_rm(acc, sM, SM_STRIDE, kc * 32, (kc & 1) ? sB1 : sB0, wm, wn, lane);
    }

    // ---------------- boundary 2->3 ----------------
    __syncthreads();
    {
        const unsigned* bs = chunk_src(wpack, 13);
#pragma unroll
        for (int i = 0; i < 4; i++) {
            int q = tid + i * 256;
            cpa16(sB_b[0] + q * 16, bs + q * 4, 16);
        }
        cpa_commit();
    }
    epi_tf32_gelu(acc, sM, SM_STRIDE, wm, wn, lane);
    init_acc(acc, sBiasAll + 256, wn, lane);

    // ---------------- stage 3: 4 chunks ----------------
#pragma unroll 1
    for (int kc = 0; kc < 4; kc++) {
        __syncthreads();
        if (kc < 3) {
            const unsigned* bs = chunk_src(wpack, 14 + kc);
#pragma unroll
            for (int i = 0; i < 4; i++) {
                int q = tid + i * 256;
                cpa16(sB_b[(kc + 1) & 1] + q * 16, bs + q * 4, 16);
            }
            cpa_commit();
            cpa_wait1();
        } else {
            cpa_wait0();
        }
        __syncthreads();
        mma_chunk_rm(acc, sM, SM_STRIDE, kc * 32, (kc & 1) ? sB1 : sB0, wm, wn, lane);
    }
    __syncthreads();  // all stage-3 MMAs done before overwriting sM

    // stage-3 epilogue: fp32 row-major into sM
    float* sMf = (float*)sM;
#pragma unroll
    for (int mt = 0; mt < 4; mt++) {
        int r0 = wm * 64 + mt * 16 + (lane >> 2);
#pragma unroll
        for (int nt = 0; nt < 4; nt++) {
            int c0 = wn * 32 + nt * 8 + (lane & 3) * 2;
            *(float2*)&sMf[r0 * SM_STRIDE + c0] = make_float2(acc[mt][nt][0], acc[mt][nt][1]);
            *(float2*)&sMf[(r0 + 8) * SM_STRIDE + c0] = make_float2(acc[mt][nt][2], acc[mt][nt][3]);
        }
    }
    __syncthreads();

    // scatter: agg[dst] += m
#pragma unroll
    for (int i = 0; i < 16; i++) {
        int lin = tid + i * 256;
        int row = lin >> 5, c4 = lin & 31;
        int d = sDst[row];
        if (d >= 0) {
            float4 v = *(float4*)&sMf[row * SM_STRIDE + c4 * 4];
            float* p = agg + (size_t)d * NCH + c4 * 4;
            asm volatile("red.global.add.v4.f32 [%0], {%1,%2,%3,%4};" ::
                             "l"(p), "f"(v.x), "f"(v.y), "f"(v.z), "f"(v.w)
                         : "memory");
        }
    }
}

// ---------------- launch ----------------
extern "C" void kernel_launch(void* const* d_in, const int* in_sizes, int n_in,
                              void* d_out, int out_size) {
    const float* x     = (const float*)d_in[0];
    const void*  ei    = d_in[1];
    const float* eattr = (const float*)d_in[2];
    const float* xpos  = (const float*)d_in[3];
    const float* w1  = (const float*)d_in[4];
    const float* b1  = (const float*)d_in[5];
    const float* mw1 = (const float*)d_in[6];
    const float* mb1 = (const float*)d_in[7];
    const float* mw2 = (const float*)d_in[8];
    const float* mb2 = (const float*)d_in[9];
    const float* mw3 = (const float*)d_in[10];
    const float* mb3 = (const float*)d_in[11];
    const float* w2  = (const float*)d_in[12];
    const float* b2  = (const float*)d_in[13];
    const float* w3  = (const float*)d_in[14];
    const float* b3  = (const float*)d_in[15];

    int N = in_sizes[0] / NCH;
    int E = in_sizes[1] / 2;
    float* out = (float*)d_out;

    float *hptr, *aptr, *tptr;
    unsigned *wp, *htf;
    cudaGetSymbolAddress((void**)&hptr, g_h);
    cudaGetSymbolAddress((void**)&aptr, g_agg);
    cudaGetSymbolAddress((void**)&tptr, g_t);
    cudaGetSymbolAddress((void**)&wp, g_wpack);
    cudaGetSymbolAddress((void**)&htf, g_htf);

    cudaFuncSetAttribute(edge_kernel, cudaFuncAttributeMaxDynamicSharedMemorySize,
                         SMEM_EDGE_BYTES);

    // launch 1
    detect_kernel<<<1, 1>>>(ei);
    // launch 2
    pack3<<<(36864 + 16384 + 16384 + 255) / 256, 256>>>(
        mw1, wp + OFF_MW1, 36864, mw2, wp + OFF_MW2, 16384, mw3, wp + OFF_MW3, 16384);
    // launch 3
    pack3<<<(3 * 16384 + 255) / 256, 256>>>(
        w1, wp + OFF_W1, 16384, w2, wp + OFF_W2, 16384, w3, wp + OFF_W3, 16384);
    // launch 4
    int n4 = N * NCH / 4;
    zero_kernel<<<(n4 + 255) / 256, 256>>>((float4*)aptr, n4);
    // launch 5
    node_gemm<<<(N + 127) / 128, 256>>>(x, nullptr, wp + OFF_W1, b1, hptr, htf, N, 0);
    // launch 6 (ncu -s 5 -c 1 captures this one)
    edge_kernel<<<(E + 127) / 128, 256, SMEM_EDGE_BYTES>>>(
        ei, eattr, xpos, htf, aptr, wp, mb1, mb2, mb3, E);
    // launch 7
    node_gemm<<<(N + 127) / 128, 256>>>(hptr, aptr, wp + OFF_W2, b2, tptr, nullptr, N, 1);
    // launch 8
    node_gemm<<<(N + 127) / 128, 256>>>(tptr, nullptr, wp + OFF_W3, b3, out, nullptr, N, 0);
}